// round 1
// baseline (speedup 1.0000x reference)
#include <cuda_runtime.h>
#include <cstdint>

// Problem shape (fixed by the reference): B=4, L=8192, D=1024.
#define BQ 4
#define LQ 8192
#define DQ 1024

// Scratch (no cudaMalloc allowed): per-batch permutation + true-counts + mask dtype mode.
__device__ int g_idx[BQ * LQ];
__device__ int g_cnt[BQ];
__device__ int g_mode;   // 0 = uint8/bool, 1 = int32, 2 = float32

// ---------------------------------------------------------------------------
// Kernel 0: detect boundary_mask storage dtype from byte pattern.
// Reads the first B*L BYTES (safe lower bound for any dtype >= 1 byte).
//   bool/uint8 : 0/1 bytes everywhere          -> offsets %4 in {1,2} ~50% nonzero
//   int32 0/1  : nonzero only at offset %4==0
//   float32    : 1.0f = 00 00 80 3F            -> nonzero only at offsets %4 in {2,3}
// Decision: c12 dominated by bool; else float32 if c3 > c0; else int32.
// ---------------------------------------------------------------------------
__global__ void detect_mask_dtype(const uint8_t* __restrict__ mask_bytes) {
    __shared__ int c0, c3, c12;
    if (threadIdx.x == 0) { c0 = 0; c3 = 0; c12 = 0; }
    __syncthreads();
    int l0 = 0, l3 = 0, l12 = 0;
    for (int i = threadIdx.x; i < BQ * LQ; i += blockDim.x) {
        int nz = (mask_bytes[i] != 0);
        int r = i & 3;
        if (r == 0)      l0  += nz;
        else if (r == 3) l3  += nz;
        else             l12 += nz;
    }
    atomicAdd(&c0, l0); atomicAdd(&c3, l3); atomicAdd(&c12, l12);
    __syncthreads();
    if (threadIdx.x == 0) {
        int mode;
        if (c12 > 1024)    mode = 0;   // dense 0/1 bytes -> bool
        else if (c3 > c0)  mode = 2;   // high byte of 1.0f -> float32
        else               mode = 1;   // low byte only -> int32
        g_mode = mode;
    }
}

// ---------------------------------------------------------------------------
// Kernel 1: per-batch stable partition. One block per batch, 256 threads,
// each thread owns a contiguous chunk of 32 tokens. Block scan of per-thread
// true-counts gives stable write offsets:
//   true token  i -> g_idx[b*L + truePrefix(i)]
//   false token i -> g_idx[b*L + totalTrue + (i - truePrefix(i))]
// ---------------------------------------------------------------------------
__global__ void build_idx_kernel(const void* __restrict__ maskp) {
    const int b = blockIdx.x;
    const int t = threadIdx.x;
    constexpr int CH = LQ / 256;   // 32 tokens per thread

    const int mode = g_mode;
    const uint8_t* m8  = (const uint8_t*)maskp + (size_t)b * LQ;
    const int*     m32 = (const int*)    maskp + (size_t)b * LQ;
    const float*   mf  = (const float*)  maskp + (size_t)b * LQ;

    const int base = t * CH;
    unsigned char v[CH];
    int cnt = 0;
    #pragma unroll
    for (int i = 0; i < CH; i++) {
        const int gi = base + i;
        int x;
        if (mode == 0)      x = (m8[gi]  != 0);
        else if (mode == 1) x = (m32[gi] != 0);
        else                x = (mf[gi]  != 0.0f);
        v[i] = (unsigned char)x;
        cnt += x;
    }

    __shared__ int s[256];
    s[t] = cnt;
    __syncthreads();
    // Hillis-Steele inclusive scan over 256 thread counts.
    for (int off = 1; off < 256; off <<= 1) {
        int x = (t >= off) ? s[t - off] : 0;
        __syncthreads();
        s[t] += x;
        __syncthreads();
    }
    const int total   = s[255];
    const int truePre = s[t] - cnt;   // exclusive prefix for this thread
    if (t == 0) g_cnt[b] = total;

    int tp = truePre;
    int fp = base - truePre;          // false-rank of first element in chunk
    int* __restrict__ gi_out = g_idx + b * LQ;
    #pragma unroll
    for (int i = 0; i < CH; i++) {
        const int gi = base + i;
        if (v[i]) gi_out[tp++]         = gi;
        else      gi_out[total + fp++] = gi;
    }
}

// ---------------------------------------------------------------------------
// Kernel 2: row gather. One block per output row (B*M blocks), 256 threads,
// each thread moves one float4 (D = 1024 floats = 256 float4).
// Thread 0 also writes the mask output element for this row.
// ---------------------------------------------------------------------------
__global__ void gather_kernel(const float* __restrict__ hs,
                              float* __restrict__ out, int M) {
    const int row = blockIdx.x;          // 0 .. B*M-1
    const int b = row / M;
    const int j = row - b * M;
    const int src = g_idx[b * LQ + j];

    const float4* __restrict__ s =
        (const float4*)(hs + ((size_t)b * LQ + (size_t)src) * DQ);
    float4* __restrict__ d = (float4*)(out + (size_t)row * DQ);
    d[threadIdx.x] = s[threadIdx.x];

    if (threadIdx.x == 0) {
        float* om = out + (size_t)BQ * M * DQ;   // mask section follows hidden states
        om[row] = (j < g_cnt[b]) ? 1.0f : 0.0f;
    }
}

// ---------------------------------------------------------------------------
extern "C" void kernel_launch(void* const* d_in, const int* in_sizes, int n_in,
                              void* d_out, int out_size) {
    const float* hs   = (const float*)d_in[0];   // hidden_states (B, L, D) f32
    const void*  mask = d_in[1];                 // boundary_mask (B, L), dtype detected
    float* out = (float*)d_out;

    // out = concat(next_hidden_states [B*M*D], next_mask [B*M])  =>  M:
    const int M = out_size / (BQ * (DQ + 1));

    detect_mask_dtype<<<1, 256>>>((const uint8_t*)mask);
    build_idx_kernel<<<BQ, 256>>>(mask);
    gather_kernel<<<BQ * M, 256>>>(hs, out, M);
}

// round 3
// speedup vs baseline: 2.6463x; 2.6463x over previous
#include <cuda_runtime.h>
#include <cstdint>

// Problem shape (fixed by the reference): B=4, L=8192, D=1024.
#define BQ 4
#define LQ 8192
#define DQ 1024

// Scratch (no cudaMalloc allowed): per-batch permutation + true-counts.
__device__ int g_idx[BQ * LQ];
__device__ int g_cnt[BQ];

// ---------------------------------------------------------------------------
// Kernel 1: per-batch stable partition (+ inline mask-dtype detection, + mask
// output). One block per batch, 256 threads, each thread owns a contiguous
// chunk of 32 tokens. Block scan of per-thread true-counts gives stable
// write offsets:
//   true token  i -> g_idx[b*L + truePrefix(i)]
//   false token i -> g_idx[b*L + totalTrue + (i - truePrefix(i))]
//
// Dtype detection (first 1024 bytes of mask, 4 bytes/thread, coalesced):
//   bool/uint8 : 0/1 at every byte         -> offset%4==1 bytes ~50% nonzero
//   int32 0/1  : nonzero only at offset 0
//   float32    : 1.0f = 00 00 80 3F        -> nonzero at offsets 2,3 only
// Rule: o1>8 -> bool; else o3>0 -> float32; else int32.
// ---------------------------------------------------------------------------
__global__ void build_idx_kernel(const void* __restrict__ maskp,
                                 float* __restrict__ out_mask, int M) {
    const int b = blockIdx.x;
    const int t = threadIdx.x;
    constexpr int CH = LQ / 256;   // 32 tokens per thread

    // --- dtype detection: 256 threads x 4 bytes = 1024 bytes sampled ---
    __shared__ int sc1, sc3;
    __shared__ int s_mode;
    if (t == 0) { sc1 = 0; sc3 = 0; }
    __syncthreads();
    {
        const uint8_t* mb = (const uint8_t*)maskp;
        uint32_t w = ((const uint32_t*)mb)[t];   // coalesced 4-byte word per thread
        int l1 = ((w >> 8)  & 0xFF) != 0;
        int l3 = ((w >> 24) & 0xFF) != 0;
        // warp-reduce then one atomic per warp
        for (int off = 16; off; off >>= 1) {
            l1 += __shfl_down_sync(0xFFFFFFFFu, l1, off);
            l3 += __shfl_down_sync(0xFFFFFFFFu, l3, off);
        }
        if ((t & 31) == 0) { atomicAdd(&sc1, l1); atomicAdd(&sc3, l3); }
    }
    __syncthreads();
    if (t == 0) {
        if (sc1 > 8)       s_mode = 0;   // bool/uint8
        else if (sc3 > 0)  s_mode = 2;   // float32
        else               s_mode = 1;   // int32
    }
    __syncthreads();
    const int mode = s_mode;

    // --- load this thread's 32-token chunk ---
    const int base = t * CH;
    unsigned char v[CH];
    int cnt = 0;
    if (mode == 0) {
        // bool fast path: 32 bytes = 2 x uint4, coalesced 16B loads
        const uint4* p = (const uint4*)((const uint8_t*)maskp + (size_t)b * LQ + base);
        uint4 q0 = p[0], q1 = p[1];
        uint32_t w[8] = {q0.x, q0.y, q0.z, q0.w, q1.x, q1.y, q1.z, q1.w};
        #pragma unroll
        for (int i = 0; i < CH; i++) {
            int x = ((w[i >> 2] >> ((i & 3) * 8)) & 0xFF) != 0;
            v[i] = (unsigned char)x;
            cnt += x;
        }
    } else if (mode == 1) {
        const int* m32 = (const int*)maskp + (size_t)b * LQ + base;
        #pragma unroll
        for (int i = 0; i < CH; i++) { int x = (m32[i] != 0); v[i] = (unsigned char)x; cnt += x; }
    } else {
        const float* mf = (const float*)maskp + (size_t)b * LQ + base;
        #pragma unroll
        for (int i = 0; i < CH; i++) { int x = (mf[i] != 0.0f); v[i] = (unsigned char)x; cnt += x; }
    }

    // --- block scan of per-thread counts ---
    __shared__ int s[256];
    s[t] = cnt;
    __syncthreads();
    for (int off = 1; off < 256; off <<= 1) {
        int x = (t >= off) ? s[t - off] : 0;
        __syncthreads();
        s[t] += x;
        __syncthreads();
    }
    const int total   = s[255];
    const int truePre = s[t] - cnt;   // exclusive prefix for this thread
    if (t == 0) g_cnt[b] = total;

    // --- scatter stable permutation ---
    int tp = truePre;
    int fp = base - truePre;
    int* __restrict__ gi_out = g_idx + b * LQ;
    #pragma unroll
    for (int i = 0; i < CH; i++) {
        const int gi = base + i;
        if (v[i]) gi_out[tp++]         = gi;
        else      gi_out[total + fp++] = gi;
    }

    // --- write this batch's slice of the mask output ---
    for (int j = t; j < M; j += 256)
        out_mask[b * M + j] = (j < total) ? 1.0f : 0.0f;
}

// ---------------------------------------------------------------------------
// Kernel 2: row gather. One block per output row (B*M blocks), 256 threads,
// each thread moves one float4 (D = 1024 floats = 256 float4). Data is
// touched exactly once -> streaming loads/stores to avoid L2 thrash.
// ---------------------------------------------------------------------------
__global__ void gather_kernel(const float* __restrict__ hs,
                              float* __restrict__ out, int M) {
    const int row = blockIdx.x;          // 0 .. B*M-1
    const int b = row / M;
    const int j = row - b * M;
    const int src = __ldg(&g_idx[b * LQ + j]);

    const float4* __restrict__ s =
        (const float4*)(hs + ((size_t)b * LQ + (size_t)src) * DQ);
    float4* __restrict__ d = (float4*)(out + (size_t)row * DQ);
    float4 val = __ldcs(s + threadIdx.x);
    __stcs(d + threadIdx.x, val);
}

// ---------------------------------------------------------------------------
extern "C" void kernel_launch(void* const* d_in, const int* in_sizes, int n_in,
                              void* d_out, int out_size) {
    const float* hs   = (const float*)d_in[0];   // hidden_states (B, L, D) f32
    const void*  mask = d_in[1];                 // boundary_mask (B, L), dtype detected
    float* out = (float*)d_out;

    // out = concat(next_hidden_states [B*M*D], next_mask [B*M])  =>  M:
    const int M = out_size / (BQ * (DQ + 1));
    float* out_mask = out + (size_t)BQ * M * DQ;

    build_idx_kernel<<<BQ, 256>>>(mask, out_mask, M);
    gather_kernel<<<BQ * M, 256>>>(hs, out, M);
}

// round 5
// speedup vs baseline: 3.1658x; 1.1963x over previous
#include <cuda_runtime.h>
#include <cstdint>

// Problem shape (fixed by the reference): B=4, L=8192, D=1024.
#define BQ 4
#define LQ 8192
#define DQ 1024

// Scratch (no cudaMalloc allowed): per-batch permutation + true-counts.
__device__ int g_idx[BQ * LQ];
__device__ int g_cnt[BQ];

// ---------------------------------------------------------------------------
// Kernel 1: per-batch stable partition (+ inline mask-dtype detection, + mask
// output). One block per batch, 512 threads, each thread owns a contiguous
// chunk of 16 tokens. Warp-shuffle block scan gives stable write offsets:
//   true token  i -> g_idx[b*L + truePrefix(i)]
//   false token i -> g_idx[b*L + totalTrue + (i - truePrefix(i))]
//
// Dtype detection (first 2048 bytes of mask, 4 bytes/thread, coalesced):
//   bool/uint8 : 0/1 at every byte         -> offset%4==1 bytes ~50% nonzero
//   int32 0/1  : nonzero only at offset 0
//   float32    : 1.0f = 00 00 80 3F        -> nonzero at offsets 2,3 only
// Rule: o1>8 -> bool; else o3>0 -> float32; else int32.
// ---------------------------------------------------------------------------
__global__ void build_idx_kernel(const void* __restrict__ maskp,
                                 float* __restrict__ out_mask, int M) {
    const int b = blockIdx.x;
    const int t = threadIdx.x;            // 0..511
    const int lane = t & 31;
    const int wid  = t >> 5;              // 0..15
    constexpr int NT = 512;
    constexpr int CH = LQ / NT;           // 16 tokens per thread

    // --- dtype detection: 512 threads x 4 bytes = 2048 bytes sampled ---
    __shared__ int sc1, sc3;
    __shared__ int s_mode;
    if (t == 0) { sc1 = 0; sc3 = 0; }
    __syncthreads();
    {
        uint32_t w = ((const uint32_t*)maskp)[t];   // coalesced word per thread
        int l1 = ((w >> 8)  & 0xFF) != 0;
        int l3 = ((w >> 24) & 0xFF) != 0;
        for (int off = 16; off; off >>= 1) {
            l1 += __shfl_down_sync(0xFFFFFFFFu, l1, off);
            l3 += __shfl_down_sync(0xFFFFFFFFu, l3, off);
        }
        if (lane == 0) { atomicAdd(&sc1, l1); atomicAdd(&sc3, l3); }
    }
    __syncthreads();
    if (t == 0) {
        if (sc1 > 8)       s_mode = 0;   // bool/uint8
        else if (sc3 > 0)  s_mode = 2;   // float32
        else               s_mode = 1;   // int32
    }
    __syncthreads();
    const int mode = s_mode;

    // --- load this thread's 16-token chunk ---
    const int base = t * CH;
    unsigned char v[CH];
    int cnt = 0;
    if (mode == 0) {
        // bool fast path: 16 bytes = 1 uint4, coalesced
        const uint4 q = *(const uint4*)((const uint8_t*)maskp + (size_t)b * LQ + base);
        uint32_t w[4] = {q.x, q.y, q.z, q.w};
        #pragma unroll
        for (int i = 0; i < CH; i++) {
            int x = ((w[i >> 2] >> ((i & 3) * 8)) & 0xFF) != 0;
            v[i] = (unsigned char)x;
            cnt += x;
        }
    } else if (mode == 1) {
        const int* m32 = (const int*)maskp + (size_t)b * LQ + base;
        #pragma unroll
        for (int i = 0; i < CH; i++) { int x = (m32[i] != 0); v[i] = (unsigned char)x; cnt += x; }
    } else {
        const float* mf = (const float*)maskp + (size_t)b * LQ + base;
        #pragma unroll
        for (int i = 0; i < CH; i++) { int x = (mf[i] != 0.0f); v[i] = (unsigned char)x; cnt += x; }
    }

    // --- block scan: warp shuffle scan + warp-total scan (2 barriers) ---
    int inc = cnt;
    #pragma unroll
    for (int off = 1; off < 32; off <<= 1) {
        int x = __shfl_up_sync(0xFFFFFFFFu, inc, off);
        if (lane >= off) inc += x;
    }
    __shared__ int wsum[16];
    if (lane == 31) wsum[wid] = inc;
    __syncthreads();
    if (wid == 0) {
        int wv = (lane < 16) ? wsum[lane] : 0;
        #pragma unroll
        for (int off = 1; off < 16; off <<= 1) {
            int x = __shfl_up_sync(0xFFFFFFFFu, wv, off);
            if (lane >= off) wv += x;
        }
        if (lane < 16) wsum[lane] = wv;   // inclusive warp prefix
    }
    __syncthreads();
    const int total   = wsum[15];
    const int truePre = (wid ? wsum[wid - 1] : 0) + inc - cnt;  // exclusive prefix
    if (t == 0) g_cnt[b] = total;

    // --- scatter stable permutation ---
    int tp = truePre;
    int fp = base - truePre;
    int* __restrict__ gi_out = g_idx + b * LQ;
    #pragma unroll
    for (int i = 0; i < CH; i++) {
        const int gi = base + i;
        if (v[i]) gi_out[tp++]         = gi;
        else      gi_out[total + fp++] = gi;
    }

    // --- write this batch's slice of the mask output ---
    for (int j = t; j < M; j += NT)
        out_mask[b * M + j] = (j < total) ? 1.0f : 0.0f;
}

// ---------------------------------------------------------------------------
// Kernel 2: row gather, 4 rows per block for MLP=4. 256 threads; thread t
// copies float4 #t of each of the block's 4 rows. All 4 LDG.128 are issued
// back-to-back (independent), then 4 STG.128. Streaming hints: data is
// touched exactly once.
// ---------------------------------------------------------------------------
#define ROWS_PER_BLK 4
__global__ void gather_kernel(const float* __restrict__ hs,
                              float* __restrict__ out, int M, int nrows) {
    const int base = blockIdx.x * ROWS_PER_BLK;
    const int t = threadIdx.x;

    float4 v[ROWS_PER_BLK];
    #pragma unroll
    for (int r = 0; r < ROWS_PER_BLK; r++) {
        int row = base + r;
        if (row < nrows) {
            int b = row / M;
            int j = row - b * M;
            int src = __ldg(&g_idx[b * LQ + j]);
            const float4* s = (const float4*)(hs + ((size_t)b * LQ + (size_t)src) * DQ);
            v[r] = __ldcs(s + t);
        }
    }
    #pragma unroll
    for (int r = 0; r < ROWS_PER_BLK; r++) {
        int row = base + r;
        if (row < nrows) {
            float4* d = (float4*)(out + (size_t)row * DQ);
            __stcs(d + t, v[r]);
        }
    }
}

// ---------------------------------------------------------------------------
extern "C" void kernel_launch(void* const* d_in, const int* in_sizes, int n_in,
                              void* d_out, int out_size) {
    const float* hs   = (const float*)d_in[0];   // hidden_states (B, L, D) f32
    const void*  mask = d_in[1];                 // boundary_mask (B, L)
    float* out = (float*)d_out;

    // out = concat(next_hidden_states [B*M*D], next_mask [B*M])  =>  M:
    const int M = out_size / (BQ * (DQ + 1));
    const int nrows = BQ * M;
    float* out_mask = out + (size_t)nrows * DQ;

    build_idx_kernel<<<BQ, 512>>>(mask, out_mask, M);
    gather_kernel<<<(nrows + ROWS_PER_BLK - 1) / ROWS_PER_BLK, 256>>>(hs, out, M, nrows);
}

// round 9
// speedup vs baseline: 3.4387x; 1.0862x over previous
#include <cuda_runtime.h>
#include <cstdint>

// Problem shape (fixed by the reference): B=4, L=8192, D=1024.
#define BQ 4
#define LQ 8192
#define DQ 1024

// Scratch (no cudaMalloc allowed): per-batch permutation + true-counts.
__device__ int g_idx[BQ * LQ];
__device__ int g_cnt[BQ];

// ---------------------------------------------------------------------------
// Kernel 1: per-batch stable partition (+ inline mask-dtype detection, + mask
// output). One block per batch, 512 threads, each thread owns a contiguous
// chunk of 16 tokens. Warp-shuffle block scan gives stable write offsets:
//   true token  i -> pos truePrefix(i)
//   false token i -> pos totalTrue + (i - truePrefix(i))
// Scattered writes go to SHARED memory (32KB staging), then one coalesced
// int4 sweep writes g_idx — avoids ~16-line STG.32 wavefront blowup.
//
// Dtype detection (first 2048 bytes of mask, 4 bytes/thread, coalesced):
//   bool/uint8 : 0/1 at every byte         -> offset%4==1 bytes ~50% nonzero
//   int32 0/1  : nonzero only at offset 0
//   float32    : 1.0f = 00 00 80 3F        -> nonzero at offsets 2,3 only
// Rule: o1>8 -> bool; else o3>0 -> float32; else int32.
// ---------------------------------------------------------------------------
__global__ void build_idx_kernel(const void* __restrict__ maskp,
                                 float* __restrict__ out_mask, int M) {
    const int b = blockIdx.x;
    const int t = threadIdx.x;            // 0..511
    const int lane = t & 31;
    const int wid  = t >> 5;              // 0..15
    constexpr int NT = 512;
    constexpr int CH = LQ / NT;           // 16 tokens per thread

    __shared__ int s_idx[LQ];             // 32KB staging for the permutation

    // --- dtype detection: 512 threads x 4 bytes = 2048 bytes sampled ---
    __shared__ int sc1, sc3;
    __shared__ int s_mode;
    if (t == 0) { sc1 = 0; sc3 = 0; }
    __syncthreads();
    {
        uint32_t w = ((const uint32_t*)maskp)[t];   // coalesced word per thread
        int l1 = ((w >> 8)  & 0xFF) != 0;
        int l3 = ((w >> 24) & 0xFF) != 0;
        for (int off = 16; off; off >>= 1) {
            l1 += __shfl_down_sync(0xFFFFFFFFu, l1, off);
            l3 += __shfl_down_sync(0xFFFFFFFFu, l3, off);
        }
        if (lane == 0) { atomicAdd(&sc1, l1); atomicAdd(&sc3, l3); }
    }
    __syncthreads();
    if (t == 0) {
        if (sc1 > 8)       s_mode = 0;   // bool/uint8
        else if (sc3 > 0)  s_mode = 2;   // float32
        else               s_mode = 1;   // int32
    }
    __syncthreads();
    const int mode = s_mode;

    // --- load this thread's 16-token chunk ---
    const int base = t * CH;
    unsigned char v[CH];
    int cnt = 0;
    if (mode == 0) {
        // bool fast path: 16 bytes = 1 uint4, coalesced
        const uint4 q = *(const uint4*)((const uint8_t*)maskp + (size_t)b * LQ + base);
        uint32_t w[4] = {q.x, q.y, q.z, q.w};
        #pragma unroll
        for (int i = 0; i < CH; i++) {
            int x = ((w[i >> 2] >> ((i & 3) * 8)) & 0xFF) != 0;
            v[i] = (unsigned char)x;
            cnt += x;
        }
    } else if (mode == 1) {
        const int* m32 = (const int*)maskp + (size_t)b * LQ + base;
        #pragma unroll
        for (int i = 0; i < CH; i++) { int x = (m32[i] != 0); v[i] = (unsigned char)x; cnt += x; }
    } else {
        const float* mf = (const float*)maskp + (size_t)b * LQ + base;
        #pragma unroll
        for (int i = 0; i < CH; i++) { int x = (mf[i] != 0.0f); v[i] = (unsigned char)x; cnt += x; }
    }

    // --- block scan: warp shuffle scan + warp-total scan (2 barriers) ---
    int inc = cnt;
    #pragma unroll
    for (int off = 1; off < 32; off <<= 1) {
        int x = __shfl_up_sync(0xFFFFFFFFu, inc, off);
        if (lane >= off) inc += x;
    }
    __shared__ int wsum[16];
    if (lane == 31) wsum[wid] = inc;
    __syncthreads();
    if (wid == 0) {
        int wv = (lane < 16) ? wsum[lane] : 0;
        #pragma unroll
        for (int off = 1; off < 16; off <<= 1) {
            int x = __shfl_up_sync(0xFFFFFFFFu, wv, off);
            if (lane >= off) wv += x;
        }
        if (lane < 16) wsum[lane] = wv;   // inclusive warp prefix
    }
    __syncthreads();
    const int total   = wsum[15];
    const int truePre = (wid ? wsum[wid - 1] : 0) + inc - cnt;  // exclusive prefix
    if (t == 0) g_cnt[b] = total;

    // --- scatter stable permutation into SMEM staging ---
    int tp = truePre;
    int fp = base - truePre;
    #pragma unroll
    for (int i = 0; i < CH; i++) {
        const int gi = base + i;
        if (v[i]) s_idx[tp++]         = gi;
        else      s_idx[total + fp++] = gi;
    }
    __syncthreads();

    // --- coalesced sweep: SMEM -> g_idx as int4 ---
    {
        const int4* src = (const int4*)s_idx;
        int4* dst = (int4*)(g_idx + b * LQ);
        #pragma unroll
        for (int j = t; j < LQ / 4; j += NT)
            dst[j] = src[j];
    }

    // --- write this batch's slice of the mask output ---
    for (int j = t; j < M; j += NT)
        out_mask[b * M + j] = (j < total) ? 1.0f : 0.0f;
}

// ---------------------------------------------------------------------------
// Kernel 2: row gather, 8 rows per block for MLP=8. 256 threads; thread t
// copies float4 #t of each of the block's 8 rows. All 8 LDG.128 issued
// back-to-back (independent), then 8 STG.128. Streaming hints: data is
// touched exactly once.
// ---------------------------------------------------------------------------
#define ROWS_PER_BLK 8
__global__ void gather_kernel(const float* __restrict__ hs,
                              float* __restrict__ out, int M, int nrows) {
    const int base = blockIdx.x * ROWS_PER_BLK;
    const int t = threadIdx.x;

    float4 v[ROWS_PER_BLK];
    #pragma unroll
    for (int r = 0; r < ROWS_PER_BLK; r++) {
        int row = base + r;
        if (row < nrows) {
            int b = row / M;
            int j = row - b * M;
            int src = __ldg(&g_idx[b * LQ + j]);
            const float4* s = (const float4*)(hs + ((size_t)b * LQ + (size_t)src) * DQ);
            v[r] = __ldcs(s + t);
        }
    }
    #pragma unroll
    for (int r = 0; r < ROWS_PER_BLK; r++) {
        int row = base + r;
        if (row < nrows) {
            float4* d = (float4*)(out + (size_t)row * DQ);
            __stcs(d + t, v[r]);
        }
    }
}

// ---------------------------------------------------------------------------
extern "C" void kernel_launch(void* const* d_in, const int* in_sizes, int n_in,
                              void* d_out, int out_size) {
    const float* hs   = (const float*)d_in[0];   // hidden_states (B, L, D) f32
    const void*  mask = d_in[1];                 // boundary_mask (B, L)
    float* out = (float*)d_out;

    // out = concat(next_hidden_states [B*M*D], next_mask [B*M])  =>  M:
    const int M = out_size / (BQ * (DQ + 1));
    const int nrows = BQ * M;
    float* out_mask = out + (size_t)nrows * DQ;

    build_idx_kernel<<<BQ, 512>>>(mask, out_mask, M);
    gather_kernel<<<(nrows + ROWS_PER_BLK - 1) / ROWS_PER_BLK, 256>>>(hs, out, M, nrows);
}